// round 1
// baseline (speedup 1.0000x reference)
#include <cuda_runtime.h>

// ---------------------------------------------------------------------------
// LocationSlayerArch: two SLAYER SNN paths (main + location), fused.
//
// Structure per path:
//   L1: pre[n,h,seq] = sum over active K-bits of W_a[h,k]   (input is binary ~10%)
//       u1 = psp(pre)      -> 2-state alpha recurrence
//       s1 = spike(u1)     -> threshold + truncated refractory (bitmask + aged
//                             2-state recurrence)
//   L2 partial: v2part[hb][n,seq,o] = sum_{h in block} s1 * W_b[o,h]
//   K2: v2 = sum_hb v2part (fixed order), psp, spike -> output
//
// main path:  seq = t, K = channel c, W_a = w_fc1,  W_b = w_fc2,  out[0:156)
// loc  path:  seq = c' (PERM order), K = t, W_a = w_loc1, W_b = w_loc2, out[156:312)
// ---------------------------------------------------------------------------

#define N_BATCH 128
#define T_SEQ   156
#define C_IN    156
#define H_DIM   1024
#define O_DIM   20
#define HB_CNT  8
#define HB_SZ   128
#define CHUNK   32
#define NWORDS  5            // ceil(156/32)

// psp (SRM alpha, tau=10):  eps(t) = (t/10) * e * lam^t,  lam = e^{-0.1}
#define LAM_S  0.90483741803595952f   // exp(-0.1)
#define K_PSP  0.27182818284590452f   // e/10
// refractory (alpha, tau=1, scale -2*theta): RK[d] = -20e * d * lr^d, d=1..15
#define LAM_R  0.36787944117144233f   // exp(-1)
#define C_REF  -54.365636569180902f   // -20*e
#define C_P16  1.1253517471925912e-07f  // exp(-16)
#define C_Q16  1.8005627955081459e-06f  // 16*exp(-16)
#define THETA  10.0f

__device__ __constant__ int c_td[39] = {
    11,25,35,4,18,30,7,2,20,37,29,12,9,33,23,16,1,6,15,21,
    27,34,39,24,17,10,31,38,28,14,3,22,32,8,19,36,5,13,26};

// scratch (device globals; no allocation in kernel_launch)
__device__ unsigned int g_xbits[2][N_BATCH * T_SEQ * NWORDS];
__device__ float g_v2part[(size_t)2 * HB_CNT * N_BATCH * T_SEQ * O_DIM]; // 51 MB

// ---------------------------------------------------------------------------
// K0: bit-pack the binary input for both paths.
//   main: bits over channel c at fixed (n,t)
//   loc : bits over time t at fixed (n,c'), channel = PERM[c']
// ---------------------------------------------------------------------------
__global__ void k_bitify(const float* __restrict__ x) {
    extern __shared__ float xs[];                 // [C_IN][T_SEQ]
    int n = blockIdx.x;
    const float* xb = x + (size_t)n * C_IN * T_SEQ;
    for (int i = threadIdx.x; i < C_IN * T_SEQ; i += blockDim.x) xs[i] = xb[i];
    __syncthreads();

    // main-path bits: word layout [n][t][w], bit j <-> channel w*32+j
    for (int task = threadIdx.x; task < T_SEQ * NWORDS; task += blockDim.x) {
        int t = task % T_SEQ;
        int w = task / T_SEQ;
        int cbase = w << 5;
        int jmax = min(32, C_IN - cbase);
        unsigned bits = 0u;
        for (int j = 0; j < jmax; j++)
            if (xs[(cbase + j) * T_SEQ + t] > 0.5f) bits |= (1u << j);
        g_xbits[0][(n * T_SEQ + t) * NWORDS + w] = bits;
    }
    // loc-path bits: word layout [n][c'][w], bit j <-> time w*32+j
    for (int task = threadIdx.x; task < T_SEQ * NWORDS; task += blockDim.x) {
        int cp = task % T_SEQ;
        int w  = task / T_SEQ;
        int blk = cp / 78;
        int j2  = cp % 78;
        int pc = 2 * c_td[j2 >> 1] - 2 + (j2 & 1) + blk * 78;   // PERM[cp]
        int tb = w << 5;
        int jmax = min(32, T_SEQ - tb);
        unsigned bits = 0u;
        for (int j = 0; j < jmax; j++)
            if (xs[pc * T_SEQ + tb + j] > 0.5f) bits |= (1u << j);
        g_xbits[1][(n * T_SEQ + cp) * NWORDS + w] = bits;
    }
}

// ---------------------------------------------------------------------------
// K1: fused layer-1 (sparse dense + psp + spike) + layer-2 partial GEMM.
// One block per (h-block, n). 128 threads = 128 hidden units.
// ---------------------------------------------------------------------------
__global__ void __launch_bounds__(HB_SZ) k_layer1(const float* __restrict__ wa,
                                                  const float* __restrict__ wb,
                                                  int path) {
    extern __shared__ float smem[];
    float* ws  = smem;                        // [C_IN][HB_SZ]  weights transposed
    float* w2s = ws + C_IN * HB_SZ;           // [HB_SZ][O_DIM]
    float* sch = w2s + HB_SZ * O_DIM;         // [CHUNK][HB_SZ] spike staging

    int hb = blockIdx.x;
    int n  = blockIdx.y;
    int tid = threadIdx.x;

    // load W_a tile (coalesced gmem, transposed into smem [c][h])
    for (int i = tid; i < HB_SZ * C_IN; i += HB_SZ) {
        int hl = i / C_IN, c = i % C_IN;
        ws[c * HB_SZ + hl] = wa[(size_t)(hb * HB_SZ + hl) * C_IN + c];
    }
    // load W_b tile into [h][o]
    for (int i = tid; i < O_DIM * HB_SZ; i += HB_SZ) {
        int o = i / HB_SZ, hl = i % HB_SZ;
        w2s[hl * O_DIM + o] = wb[(size_t)o * H_DIM + hb * HB_SZ + hl];
    }
    __syncthreads();

    const unsigned* xb = g_xbits[path] + n * T_SEQ * NWORDS;
    float* vout = g_v2part +
        ((size_t)(path * HB_CNT + hb) * N_BATCH + n) * (T_SEQ * O_DIM);

    float A = 0.f, B = 0.f;          // psp states
    float P = 0.f, Q = 0.f;          // refractory states
    unsigned hist = 0u;              // spike history bits (bit k = s[t-1-k])

    for (int t0 = 0; t0 < T_SEQ; t0 += CHUNK) {
        int clen = min(CHUNK, T_SEQ - t0);
        for (int tl = 0; tl < clen; tl++) {
            int t = t0 + tl;
            // sparse dense: sum of active weight columns (uniform bit scan)
            float acc = 0.0f;
            #pragma unroll
            for (int w = 0; w < NWORDS; w++) {
                unsigned m = xb[t * NWORDS + w];
                while (m) {
                    int c = (w << 5) + (__ffs(m) - 1);
                    m &= m - 1u;
                    acc += ws[c * HB_SZ + tid];
                }
            }
            // psp recurrence (alpha kernel)
            B = LAM_S * (B + A);
            A = LAM_S * A + acc;
            float u  = K_PSP * B;
            // refractory: ref = C_REF * Q (Q tracks truncated 15-tap alpha)
            float um = u + C_REF * Q;
            unsigned sb = (um >= THETA) ? 1u : 0u;
            float s = (float)sb;
            float aged = (float)((hist >> 14) & 1u);   // s[t-15] ages out
            Q = LAM_R * (Q + P + s) - aged * C_Q16;
            P = LAM_R * (P + s)     - aged * C_P16;
            hist = (hist << 1) | sb;
            sch[tl * HB_SZ + tid] = s;
        }
        __syncthreads();
        // layer-2 partial for this chunk: v2part[t,o] = sum_h s[t,h]*W_b[o,h]
        for (int idx = tid; idx < clen * O_DIM; idx += HB_SZ) {
            int tl = idx / O_DIM, o = idx % O_DIM;
            const float* srow = sch + tl * HB_SZ;
            float p = 0.0f;
            #pragma unroll 8
            for (int h = 0; h < HB_SZ; h++)
                p += srow[h] * w2s[h * O_DIM + o];
            vout[(t0 + tl) * O_DIM + o] = p;
        }
        __syncthreads();
    }
}

// ---------------------------------------------------------------------------
// K2: sum the 8 h-block partials (fixed order), psp + spike, write output.
// Output layout: [n][o][312]; main at [0,156), loc at [156,312).
// ---------------------------------------------------------------------------
__global__ void k_layer2(float* __restrict__ out) {
    int gid = blockIdx.x * blockDim.x + threadIdx.x;
    if (gid >= 2 * N_BATCH * O_DIM) return;
    int path = gid / (N_BATCH * O_DIM);
    int r = gid % (N_BATCH * O_DIM);
    int n = r / O_DIM, o = r % O_DIM;

    const size_t slab = (size_t)N_BATCH * T_SEQ * O_DIM;
    const float* base = g_v2part + (size_t)path * HB_CNT * slab
                        + (size_t)n * (T_SEQ * O_DIM) + o;
    float* op = out + ((size_t)n * O_DIM + o) * 312 + path * T_SEQ;

    float A = 0.f, B = 0.f, P = 0.f, Q = 0.f;
    unsigned hist = 0u;
    for (int t = 0; t < T_SEQ; t++) {
        float pre = 0.0f;
        #pragma unroll
        for (int hb = 0; hb < HB_CNT; hb++)
            pre += base[(size_t)hb * slab + t * O_DIM];
        B = LAM_S * (B + A);
        A = LAM_S * A + pre;
        float u  = K_PSP * B;
        float um = u + C_REF * Q;
        unsigned sb = (um >= THETA) ? 1u : 0u;
        float s = (float)sb;
        float aged = (float)((hist >> 14) & 1u);
        Q = LAM_R * (Q + P + s) - aged * C_Q16;
        P = LAM_R * (P + s)     - aged * C_P16;
        hist = (hist << 1) | sb;
        op[t] = s;
    }
}

// ---------------------------------------------------------------------------
extern "C" void kernel_launch(void* const* d_in, const int* in_sizes, int n_in,
                              void* d_out, int out_size) {
    const float* x   = (const float*)d_in[0];   // [128,156,1,1,156]
    const float* w1  = (const float*)d_in[1];   // [1024,156]
    const float* w2  = (const float*)d_in[2];   // [20,1024]
    const float* wl1 = (const float*)d_in[3];   // [1024,156]
    const float* wl2 = (const float*)d_in[4];   // [20,1024]
    float* out = (float*)d_out;                 // [128,20,1,1,312]

    const int SM0 = C_IN * T_SEQ * 4;                                   // 97344
    const int SM1 = (C_IN * HB_SZ + HB_SZ * O_DIM + CHUNK * HB_SZ) * 4; // 106496
    cudaFuncSetAttribute(k_bitify, cudaFuncAttributeMaxDynamicSharedMemorySize, SM0);
    cudaFuncSetAttribute(k_layer1, cudaFuncAttributeMaxDynamicSharedMemorySize, SM1);

    k_bitify<<<N_BATCH, 256, SM0>>>(x);

    dim3 g1(HB_CNT, N_BATCH);
    k_layer1<<<g1, HB_SZ, SM1>>>(w1,  w2,  0);   // main path
    k_layer1<<<g1, HB_SZ, SM1>>>(wl1, wl2, 1);   // location path

    k_layer2<<<(2 * N_BATCH * O_DIM + 255) / 256, 256>>>(out);
}

// round 2
// speedup vs baseline: 2.8366x; 2.8366x over previous
#include <cuda_runtime.h>

// ---------------------------------------------------------------------------
// LocationSlayerArch, round 2: split parallel work out of the serial scan.
//   k_bitify : pack active-input index lists (premultiplied byte offsets)
//   k_gemm1  : sparse layer-1 GEMM, parallel over (path,n,hb,t)  -> g_pre
//   k_neuron1: psp+spike recurrence (high occupancy) + sparse L2 partial
//   k_reduce2: sum 8 h-block partials (wide parallel)
//   k_spike2 : layer-2 recurrence + output
// ---------------------------------------------------------------------------

#define N_BATCH 128
#define T_SEQ   156
#define C_IN    156
#define H_DIM   1024
#define O_DIM   20
#define HB_CNT  8
#define HB_SZ   128
#define IDX_CAP 160
#define WS_STRIDE 130                 // padded row stride (floats), 8B aligned
#define ROW_BYTES (WS_STRIDE * 4)     // 520

// psp (SRM alpha, tau=10):  eps(t) = (t/10) * e * lam^t,  lam = e^{-0.1}
#define LAM_S  0.90483741803595952f
#define K_PSP  0.27182818284590452f
// refractory (alpha, tau=1, scale -2*theta), 15-tap truncation via aging
#define LAM_R  0.36787944117144233f
#define C_REF  -54.365636569180902f
#define C_P16  1.1253517471925912e-07f
#define C_Q16  1.8005627955081459e-06f
#define THETA  10.0f

__device__ __constant__ int c_td[39] = {
    11,25,35,4,18,30,7,2,20,37,29,12,9,33,23,16,1,6,15,21,
    27,34,39,24,17,10,31,38,28,14,3,22,32,8,19,36,5,13,26};

// scratch (device globals; no allocation in kernel_launch)
__device__ unsigned g_idx[(size_t)2 * N_BATCH * T_SEQ * IDX_CAP];   // ~25.6MB
__device__ int      g_cnt[2 * N_BATCH * T_SEQ];
__device__ float    g_pre[(size_t)2 * N_BATCH * HB_CNT * T_SEQ * HB_SZ];   // 163MB
__device__ float    g_v2part[(size_t)2 * HB_CNT * N_BATCH * T_SEQ * O_DIM]; // 51MB
__device__ float    g_v2[(size_t)2 * N_BATCH * T_SEQ * O_DIM];             // 3.2MB

// ---------------------------------------------------------------------------
// K0: build active-index lists for both paths.
//   main: seq=t, indices over channel c.   loc: seq=c' (PERM), indices over t.
// Index values are premultiplied byte row-offsets (c*520); padded to x4 with
// a dummy zero row (156*520).
// ---------------------------------------------------------------------------
__global__ void k_bitify(const float* __restrict__ x) {
    extern __shared__ float xs[];                 // [C_IN][T_SEQ]
    int n = blockIdx.x;
    const float* xb = x + (size_t)n * C_IN * T_SEQ;
    for (int i = threadIdx.x; i < C_IN * T_SEQ; i += blockDim.x) xs[i] = xb[i];
    __syncthreads();

    for (int task = threadIdx.x; task < 2 * T_SEQ; task += blockDim.x) {
        int path = task / T_SEQ, seq = task % T_SEQ;
        unsigned* ob = g_idx + ((size_t)(path * N_BATCH + n) * T_SEQ + seq) * IDX_CAP;
        int cnt = 0;
        if (path == 0) {
            int t = seq;
            for (int c = 0; c < C_IN; c++)
                if (xs[c * T_SEQ + t] > 0.5f) ob[cnt++] = (unsigned)(c * ROW_BYTES);
        } else {
            int cp = seq;
            int blk = cp / 78, j2 = cp % 78;
            int pc = 2 * c_td[j2 >> 1] - 2 + (j2 & 1) + blk * 78;   // PERM[cp]
            for (int t = 0; t < T_SEQ; t++)
                if (xs[pc * T_SEQ + t] > 0.5f) ob[cnt++] = (unsigned)(t * ROW_BYTES);
        }
        while (cnt & 3) ob[cnt++] = (unsigned)(C_IN * ROW_BYTES);  // dummy zero row
        g_cnt[(path * N_BATCH + n) * T_SEQ + seq] = cnt;
    }
}

// ---------------------------------------------------------------------------
// K1a: sparse GEMM1. grid (hb, n), 256 threads = 4 t-strips x 64 h-pairs.
// Each thread accumulates 2 hidden units with packed f32x2 adds.
// ---------------------------------------------------------------------------
__global__ void __launch_bounds__(256) k_gemm1(const float* __restrict__ wa, int path) {
    extern __shared__ float ws[];   // [157][130] floats; row 156 = zeros
    int hb = blockIdx.x, n = blockIdx.y, tid = threadIdx.x;

    for (int i = tid; i < HB_SZ * C_IN; i += 256) {
        int hl = i / C_IN, c = i % C_IN;
        ws[c * WS_STRIDE + hl] = wa[(size_t)(hb * HB_SZ + hl) * C_IN + c];
    }
    for (int i = tid; i < WS_STRIDE; i += 256) ws[C_IN * WS_STRIDE + i] = 0.0f;
    __syncthreads();

    int strip = tid >> 6;
    int hp = tid & 63;
    const char* wsb = (const char*)ws + hp * 8;
    float* pp = g_pre + (size_t)((path * N_BATCH + n) * HB_CNT + hb) * (T_SEQ * HB_SZ);
    const int seqbase = (path * N_BATCH + n) * T_SEQ;

    int t0 = strip * 39, t1 = t0 + 39;
    for (int t = t0; t < t1; t++) {
        const unsigned* ib = g_idx + (size_t)(seqbase + t) * IDX_CAP;
        int cnt = g_cnt[seqbase + t];
        unsigned long long acc = 0ULL;   // packed {0.0f, 0.0f}
        for (int k = 0; k < cnt; k += 4) {
            uint4 v = *(const uint4*)(ib + k);
            unsigned long long a0 = *(const unsigned long long*)(wsb + v.x);
            unsigned long long a1 = *(const unsigned long long*)(wsb + v.y);
            unsigned long long a2 = *(const unsigned long long*)(wsb + v.z);
            unsigned long long a3 = *(const unsigned long long*)(wsb + v.w);
            asm("add.rn.f32x2 %0, %0, %1;" : "+l"(acc) : "l"(a0));
            asm("add.rn.f32x2 %0, %0, %1;" : "+l"(acc) : "l"(a1));
            asm("add.rn.f32x2 %0, %0, %1;" : "+l"(acc) : "l"(a2));
            asm("add.rn.f32x2 %0, %0, %1;" : "+l"(acc) : "l"(a3));
        }
        *(float2*)(pp + t * HB_SZ + hp * 2) = *(float2*)&acc;
    }
}

// ---------------------------------------------------------------------------
// K1b: layer-1 recurrence (psp + spike w/ refractory) + sparse L2 partial.
// grid (hb, n), 128 threads (one per hidden unit). High occupancy.
// ---------------------------------------------------------------------------
__global__ void __launch_bounds__(HB_SZ) k_neuron1(const float* __restrict__ wb, int path) {
    __shared__ float w2s[HB_SZ * O_DIM];      // [h][o]
    __shared__ unsigned sb[T_SEQ * 4];        // spike bitmasks per t (4 warps)

    int hb = blockIdx.x, n = blockIdx.y, tid = threadIdx.x;
    int lane = tid & 31, wrp = tid >> 5;

    for (int i = tid; i < O_DIM * HB_SZ; i += HB_SZ) {
        int h = i % HB_SZ, o = i / HB_SZ;
        w2s[h * O_DIM + o] = wb[(size_t)o * H_DIM + hb * HB_SZ + h];
    }
    __syncthreads();

    const float* pp = g_pre + (size_t)((path * N_BATCH + n) * HB_CNT + hb) * (T_SEQ * HB_SZ);

    float A = 0.f, B = 0.f, P = 0.f, Q = 0.f;
    unsigned hist = 0u;
    #pragma unroll 4
    for (int t = 0; t < T_SEQ; t++) {
        float acc = pp[t * HB_SZ + tid];
        B = LAM_S * (B + A);
        A = LAM_S * A + acc;
        float u  = K_PSP * B;
        float um = u + C_REF * Q;
        unsigned spk = (um >= THETA) ? 1u : 0u;
        float s = (float)spk;
        float aged = (float)((hist >> 14) & 1u);
        Q = LAM_R * (Q + P + s) - aged * C_Q16;
        P = LAM_R * (P + s)     - aged * C_P16;
        hist = (hist << 1) | spk;
        unsigned bal = __ballot_sync(0xffffffffu, spk);
        if (lane == 0) sb[t * 4 + wrp] = bal;
    }
    __syncthreads();

    // L2 partial over set bits only (exact: skipping s==0 terms)
    float* vout = g_v2part + (size_t)((path * HB_CNT + hb) * N_BATCH + n) * (T_SEQ * O_DIM);
    for (int task = tid; task < T_SEQ * O_DIM; task += HB_SZ) {
        int t = task / O_DIM, o = task % O_DIM;
        float acc = 0.f;
        #pragma unroll
        for (int wd = 0; wd < 4; wd++) {
            unsigned m = sb[t * 4 + wd];
            const float* wcol = w2s + wd * 32 * O_DIM + o;
            while (m) {
                int j = __ffs(m) - 1;
                m &= m - 1u;
                acc += wcol[j * O_DIM];
            }
        }
        vout[task] = acc;
    }
}

// ---------------------------------------------------------------------------
// K2a: reduce 8 h-block partials (fixed ascending order).
// ---------------------------------------------------------------------------
#define SLAB (N_BATCH * T_SEQ * O_DIM)   // 399360
__global__ void k_reduce2() {
    int gid = blockIdx.x * blockDim.x + threadIdx.x;
    if (gid >= 2 * SLAB) return;
    int path = gid / SLAB, r = gid % SLAB;
    const float* base = g_v2part + (size_t)path * HB_CNT * SLAB + r;
    float acc = 0.f;
    #pragma unroll
    for (int hb = 0; hb < HB_CNT; hb++) acc += base[(size_t)hb * SLAB];
    g_v2[gid] = acc;
}

// ---------------------------------------------------------------------------
// K2b: layer-2 recurrence + output. 5120 threads.
// out layout: [n][o][312]; main at [0,156), loc at [156,312).
// ---------------------------------------------------------------------------
__global__ void k_spike2(float* __restrict__ out) {
    int gid = blockIdx.x * blockDim.x + threadIdx.x;
    if (gid >= 2 * N_BATCH * O_DIM) return;
    int path = gid / (N_BATCH * O_DIM);
    int r = gid % (N_BATCH * O_DIM);
    int n = r / O_DIM, o = r % O_DIM;

    const float* vp = g_v2 + (size_t)path * SLAB + n * (T_SEQ * O_DIM) + o;
    float* op = out + ((size_t)n * O_DIM + o) * 312 + path * T_SEQ;

    float A = 0.f, B = 0.f, P = 0.f, Q = 0.f;
    unsigned hist = 0u;
    #pragma unroll 4
    for (int t = 0; t < T_SEQ; t++) {
        float pre = vp[t * O_DIM];
        B = LAM_S * (B + A);
        A = LAM_S * A + pre;
        float u  = K_PSP * B;
        float um = u + C_REF * Q;
        unsigned spk = (um >= THETA) ? 1u : 0u;
        float s = (float)spk;
        float aged = (float)((hist >> 14) & 1u);
        Q = LAM_R * (Q + P + s) - aged * C_Q16;
        P = LAM_R * (P + s)     - aged * C_P16;
        hist = (hist << 1) | spk;
        op[t] = s;
    }
}

// ---------------------------------------------------------------------------
extern "C" void kernel_launch(void* const* d_in, const int* in_sizes, int n_in,
                              void* d_out, int out_size) {
    const float* x   = (const float*)d_in[0];
    const float* w1  = (const float*)d_in[1];
    const float* w2  = (const float*)d_in[2];
    const float* wl1 = (const float*)d_in[3];
    const float* wl2 = (const float*)d_in[4];
    float* out = (float*)d_out;

    const int SM0 = C_IN * T_SEQ * 4;                 // 97344
    const int SM1 = (C_IN + 1) * WS_STRIDE * 4;       // 81640
    cudaFuncSetAttribute(k_bitify, cudaFuncAttributeMaxDynamicSharedMemorySize, SM0);
    cudaFuncSetAttribute(k_gemm1,  cudaFuncAttributeMaxDynamicSharedMemorySize, SM1);

    k_bitify<<<N_BATCH, 256, SM0>>>(x);

    dim3 g1(HB_CNT, N_BATCH);
    k_gemm1<<<g1, 256, SM1>>>(w1,  0);
    k_gemm1<<<g1, 256, SM1>>>(wl1, 1);
    k_neuron1<<<g1, HB_SZ>>>(w2,  0);
    k_neuron1<<<g1, HB_SZ>>>(wl2, 1);

    k_reduce2<<<(2 * SLAB + 255) / 256, 256>>>();
    k_spike2<<<(2 * N_BATCH * O_DIM + 255) / 256, 256>>>(out);
}

// round 3
// speedup vs baseline: 4.0412x; 1.4247x over previous
#include <cuda_runtime.h>
#include <cstdint>

// ---------------------------------------------------------------------------
// LocationSlayerArch, round 3: merged-path launches + 4h/thread sparse gemm.
//   k_bitify : active-input index lists (premultiplied byte offsets)
//   k_gemm1  : sparse layer-1 GEMM (both paths, grid.z)  -> g_pre
//   k_neuron1: psp+spike recurrence + sparse L2 partial (both paths)
//   k_final  : hb-reduction + layer-2 recurrence + output
// ---------------------------------------------------------------------------

#define N_BATCH 128
#define T_SEQ   156
#define C_IN    156
#define H_DIM   1024
#define O_DIM   20
#define HB_CNT  8
#define HB_SZ   128
#define IDX_CAP 160
#define WS_STRIDE 132                 // padded row stride (floats), 16B aligned
#define ROW_BYTES (WS_STRIDE * 4)     // 528

#define LAM_S  0.90483741803595952f
#define K_PSP  0.27182818284590452f
#define LAM_R  0.36787944117144233f
#define C_REF  -54.365636569180902f
#define C_P16  1.1253517471925912e-07f
#define C_Q16  1.8005627955081459e-06f
#define THETA  10.0f

__device__ __constant__ int c_td[39] = {
    11,25,35,4,18,30,7,2,20,37,29,12,9,33,23,16,1,6,15,21,
    27,34,39,24,17,10,31,38,28,14,3,22,32,8,19,36,5,13,26};

__device__ unsigned g_idx[(size_t)2 * N_BATCH * T_SEQ * IDX_CAP];
__device__ int      g_cnt[2 * N_BATCH * T_SEQ];
__device__ float    g_pre[(size_t)2 * N_BATCH * HB_CNT * T_SEQ * HB_SZ];    // 163MB
__device__ float    g_v2part[(size_t)2 * HB_CNT * N_BATCH * T_SEQ * O_DIM]; // 51MB

// ---------------------------------------------------------------------------
// K0: build active-index lists. grid (n, path), 160 threads.
// ---------------------------------------------------------------------------
__global__ void __launch_bounds__(160) k_bitify(const float* __restrict__ x) {
    extern __shared__ float xs[];                 // [C_IN][T_SEQ]
    int n = blockIdx.x, path = blockIdx.y;
    const float* xb = x + (size_t)n * C_IN * T_SEQ;
    for (int i = threadIdx.x; i < C_IN * T_SEQ; i += blockDim.x) xs[i] = xb[i];
    __syncthreads();

    int seq = threadIdx.x;
    if (seq >= T_SEQ) return;
    unsigned* ob = g_idx + ((size_t)(path * N_BATCH + n) * T_SEQ + seq) * IDX_CAP;
    int cnt = 0;
    if (path == 0) {
        int t = seq;
        for (int c = 0; c < C_IN; c++)
            if (xs[c * T_SEQ + t] > 0.5f) ob[cnt++] = (unsigned)(c * ROW_BYTES);
    } else {
        int cp = seq;
        int blk = cp / 78, j2 = cp % 78;
        int pc = 2 * c_td[j2 >> 1] - 2 + (j2 & 1) + blk * 78;   // PERM[cp]
        for (int t = 0; t < T_SEQ; t++)
            if (xs[pc * T_SEQ + t] > 0.5f) ob[cnt++] = (unsigned)(t * ROW_BYTES);
    }
    while (cnt & 3) ob[cnt++] = (unsigned)(C_IN * ROW_BYTES);  // dummy zero row
    g_cnt[(path * N_BATCH + n) * T_SEQ + seq] = cnt;
}

// ---------------------------------------------------------------------------
// K1a: sparse GEMM1. grid (hb, n, path), 256 threads = 8 warps.
// Warp = one t-strip (t = warp; t += 8). Lane owns 4 hidden units (lane*4..+3).
// Inner op per active index: IADD + LDS.128 (v2.b64) + 2x add.rn.f32x2.
// ---------------------------------------------------------------------------
__global__ void __launch_bounds__(256) k_gemm1(const float* __restrict__ w_main,
                                               const float* __restrict__ w_loc) {
    extern __shared__ float ws[];   // [157][132]; row 156 = zeros
    int hb = blockIdx.x, n = blockIdx.y, path = blockIdx.z;
    int tid = threadIdx.x;
    const float* wa = path ? w_loc : w_main;

    for (int i = tid; i < HB_SZ * C_IN; i += 256) {
        int hl = i / C_IN, c = i % C_IN;
        ws[c * WS_STRIDE + hl] = wa[(size_t)(hb * HB_SZ + hl) * C_IN + c];
    }
    for (int i = tid; i < WS_STRIDE; i += 256) ws[C_IN * WS_STRIDE + i] = 0.0f;
    __syncthreads();

    uint32_t ws32;
    asm("{ .reg .u64 t; cvta.to.shared.u64 t, %1; cvt.u32.u64 %0, t; }"
        : "=r"(ws32) : "l"(ws));

    int wrp = tid >> 5, lane = tid & 31;
    uint32_t base = ws32 + lane * 16;
    float* pp = g_pre + (size_t)((path * N_BATCH + n) * HB_CNT + hb) * (T_SEQ * HB_SZ);
    const int seqbase = (path * N_BATCH + n) * T_SEQ;

    for (int t = wrp; t < T_SEQ; t += 8) {
        const unsigned* ib = g_idx + (size_t)(seqbase + t) * IDX_CAP;
        int cnt = g_cnt[seqbase + t];
        unsigned long long acc0 = 0ULL, acc1 = 0ULL;
        for (int k = 0; k < cnt; k += 4) {
            uint4 v = *(const uint4*)(ib + k);
            unsigned long long a, b;
            asm volatile("ld.shared.v2.b64 {%0,%1}, [%2];" : "=l"(a), "=l"(b) : "r"(base + v.x));
            asm("add.rn.f32x2 %0, %0, %1;" : "+l"(acc0) : "l"(a));
            asm("add.rn.f32x2 %0, %0, %1;" : "+l"(acc1) : "l"(b));
            asm volatile("ld.shared.v2.b64 {%0,%1}, [%2];" : "=l"(a), "=l"(b) : "r"(base + v.y));
            asm("add.rn.f32x2 %0, %0, %1;" : "+l"(acc0) : "l"(a));
            asm("add.rn.f32x2 %0, %0, %1;" : "+l"(acc1) : "l"(b));
            asm volatile("ld.shared.v2.b64 {%0,%1}, [%2];" : "=l"(a), "=l"(b) : "r"(base + v.z));
            asm("add.rn.f32x2 %0, %0, %1;" : "+l"(acc0) : "l"(a));
            asm("add.rn.f32x2 %0, %0, %1;" : "+l"(acc1) : "l"(b));
            asm volatile("ld.shared.v2.b64 {%0,%1}, [%2];" : "=l"(a), "=l"(b) : "r"(base + v.w));
            asm("add.rn.f32x2 %0, %0, %1;" : "+l"(acc0) : "l"(a));
            asm("add.rn.f32x2 %0, %0, %1;" : "+l"(acc1) : "l"(b));
        }
        uint2 u0 = *reinterpret_cast<uint2*>(&acc0);
        uint2 u1 = *reinterpret_cast<uint2*>(&acc1);
        float4 r;
        r.x = __uint_as_float(u0.x); r.y = __uint_as_float(u0.y);
        r.z = __uint_as_float(u1.x); r.w = __uint_as_float(u1.y);
        *(float4*)(pp + t * HB_SZ + lane * 4) = r;
    }
}

// ---------------------------------------------------------------------------
// K1b: layer-1 recurrence + sparse L2 partial. grid (hb, n, path), 128 thr.
// ---------------------------------------------------------------------------
__global__ void __launch_bounds__(HB_SZ) k_neuron1(const float* __restrict__ wb_main,
                                                   const float* __restrict__ wb_loc) {
    __shared__ float w2s[HB_SZ * O_DIM];      // [h][o]
    __shared__ unsigned sb[T_SEQ * 4];        // spike bitmasks per t (4 warps)

    int hb = blockIdx.x, n = blockIdx.y, path = blockIdx.z;
    int tid = threadIdx.x;
    int lane = tid & 31, wrp = tid >> 5;
    const float* wb = path ? wb_loc : wb_main;

    for (int i = tid; i < O_DIM * HB_SZ; i += HB_SZ) {
        int h = i % HB_SZ, o = i / HB_SZ;
        w2s[h * O_DIM + o] = wb[(size_t)o * H_DIM + hb * HB_SZ + h];
    }
    __syncthreads();

    const float* pp = g_pre + (size_t)((path * N_BATCH + n) * HB_CNT + hb) * (T_SEQ * HB_SZ);

    float A = 0.f, B = 0.f, P = 0.f, Q = 0.f;
    unsigned hist = 0u;
    #pragma unroll 4
    for (int t = 0; t < T_SEQ; t++) {
        float acc = pp[t * HB_SZ + tid];
        B = LAM_S * (B + A);
        A = LAM_S * A + acc;
        float u  = K_PSP * B;
        float um = u + C_REF * Q;
        unsigned spk = (um >= THETA) ? 1u : 0u;
        float s = (float)spk;
        float aged = (float)((hist >> 14) & 1u);
        Q = LAM_R * (Q + P + s) - aged * C_Q16;
        P = LAM_R * (P + s)     - aged * C_P16;
        hist = (hist << 1) | spk;
        unsigned bal = __ballot_sync(0xffffffffu, spk);
        if (lane == 0) sb[t * 4 + wrp] = bal;
    }
    __syncthreads();

    float* vout = g_v2part + (size_t)((path * HB_CNT + hb) * N_BATCH + n) * (T_SEQ * O_DIM);
    for (int task = tid; task < T_SEQ * O_DIM; task += HB_SZ) {
        int t = task / O_DIM, o = task % O_DIM;
        float acc = 0.f;
        #pragma unroll
        for (int wd = 0; wd < 4; wd++) {
            unsigned m = sb[t * 4 + wd];
            const float* wcol = w2s + wd * 32 * O_DIM + o;
            while (m) {
                int j = __ffs(m) - 1;
                m &= m - 1u;
                acc += wcol[j * O_DIM];
            }
        }
        vout[task] = acc;
    }
}

// ---------------------------------------------------------------------------
// K2: sum 8 h-block partials into smem, then layer-2 recurrence + output.
// grid 256 = (path, n), 128 threads.
// out layout: [n][o][312]; main at [0,156), loc at [156,312).
// ---------------------------------------------------------------------------
#define TO (T_SEQ * O_DIM)   // 3120
__global__ void __launch_bounds__(128) k_final(float* __restrict__ out) {
    __shared__ float v[TO];
    int b = blockIdx.x;
    int path = b >> 7, n = b & 127;
    int tid = threadIdx.x;

    const float* base = g_v2part + (size_t)(path * HB_CNT * N_BATCH + n) * TO;
    for (int i = tid; i < TO; i += 128) {
        float acc = 0.f;
        #pragma unroll
        for (int hb = 0; hb < HB_CNT; hb++)
            acc += base[(size_t)hb * N_BATCH * TO + i];
        v[i] = acc;
    }
    __syncthreads();

    if (tid < O_DIM) {
        int o = tid;
        float* op = out + ((size_t)n * O_DIM + o) * 312 + path * T_SEQ;
        float A = 0.f, B = 0.f, P = 0.f, Q = 0.f;
        unsigned hist = 0u;
        #pragma unroll 4
        for (int t = 0; t < T_SEQ; t++) {
            float pre = v[t * O_DIM + o];
            B = LAM_S * (B + A);
            A = LAM_S * A + pre;
            float u  = K_PSP * B;
            float um = u + C_REF * Q;
            unsigned spk = (um >= THETA) ? 1u : 0u;
            float s = (float)spk;
            float aged = (float)((hist >> 14) & 1u);
            Q = LAM_R * (Q + P + s) - aged * C_Q16;
            P = LAM_R * (P + s)     - aged * C_P16;
            hist = (hist << 1) | spk;
            op[t] = s;
        }
    }
}

// ---------------------------------------------------------------------------
extern "C" void kernel_launch(void* const* d_in, const int* in_sizes, int n_in,
                              void* d_out, int out_size) {
    const float* x   = (const float*)d_in[0];
    const float* w1  = (const float*)d_in[1];
    const float* w2  = (const float*)d_in[2];
    const float* wl1 = (const float*)d_in[3];
    const float* wl2 = (const float*)d_in[4];
    float* out = (float*)d_out;

    const int SM0 = C_IN * T_SEQ * 4;                 // 97344
    const int SM1 = (C_IN + 1) * WS_STRIDE * 4;       // 82896
    cudaFuncSetAttribute(k_bitify, cudaFuncAttributeMaxDynamicSharedMemorySize, SM0);
    cudaFuncSetAttribute(k_gemm1,  cudaFuncAttributeMaxDynamicSharedMemorySize, SM1);

    dim3 g0(N_BATCH, 2);
    k_bitify<<<g0, 160, SM0>>>(x);

    dim3 g1(HB_CNT, N_BATCH, 2);
    k_gemm1<<<g1, 256, SM1>>>(w1, wl1);
    k_neuron1<<<g1, HB_SZ>>>(w2, wl2);

    k_final<<<2 * N_BATCH, 128>>>(out);
}